// round 1
// baseline (speedup 1.0000x reference)
#include <cuda_runtime.h>
#include <cstdint>
#include <cstddef>

// Problem constants
#define BATCH 256
#define ANUM  128
#define NBNUM 256
#define DNUM  16
#define FA    64
#define FB    32
#define FPC   256          // output channels
#define R_NEI  (BATCH*ANUM*DNUM)   // 524288 rows
#define R_ATOM (BATCH*ANUM)        // 32768 rows
#define ATOM_OUT_ELEMS ((long long)R_ATOM*FPC)   //   8,388,608
#define NEI_OUT_ELEMS  ((long long)R_NEI*FPC)    // 134,217,728
#define BN_EPS 1e-6f
#define SLOPE  0.01f

// ---------------- device scratch (no allocations allowed) ----------------
__device__ float g_sum[2][FPC];
__device__ float g_sqsum[2][FPC];
__device__ float g_scale[2][FPC];
__device__ float g_shift[2][FPC];

__global__ void zero_stats_kernel() {
    int t = threadIdx.x;
    if (t < FPC) {
        g_sum[0][t] = 0.f;  g_sum[1][t] = 0.f;
        g_sqsum[0][t] = 0.f; g_sqsum[1][t] = 0.f;
    }
}

// ---------------- packed f32x2 helpers (FFMA2 only reachable via PTX) ----
__device__ __forceinline__ unsigned long long pack2(float lo, float hi) {
    unsigned long long r;
    asm("mov.b64 %0, {%1,%2};" : "=l"(r) : "f"(lo), "f"(hi));
    return r;
}
__device__ __forceinline__ void fma2(unsigned long long& d,
                                     unsigned long long a,
                                     unsigned long long b) {
    asm("fma.rn.f32x2 %0, %1, %2, %0;" : "+l"(d) : "l"(a), "l"(b));
}
__device__ __forceinline__ float2 unpack2(unsigned long long v) {
    float2 r;
    asm("mov.b64 {%0,%1}, %2;" : "=f"(r.x), "=f"(r.y) : "l"(v));
    return r;
}

// ---------------- fused GEMM + raw store + channel-stat accumulation -----
// Tile: 64 rows x 256 channels per block, 256 threads.
// Thread (tr=tid>>5, tc=tid&31) owns rows [tr*8, tr*8+8) x channels [tc*8, tc*8+8).
// W staged transposed in shared once per block; grid-stride over row tiles.
template<int K, bool GATHER>
__global__ __launch_bounds__(256, 1)
void gemm_bn_kernel(const float4* __restrict__ Wg,   // [FPC][K/4]
                    const float*  __restrict__ bias, // [FPC]
                    const float4* __restrict__ af,   // GATHER: atom feats [B*A][FA/4]; else rows [R][K/4]
                    const float4* __restrict__ bf,   // GATHER: bond feats [B*NB][FB/4]
                    const int*    __restrict__ nl,   // [R_NEI]
                    const int*    __restrict__ bl,   // [R_NEI]
                    float*        __restrict__ out,
                    int statsIdx, int numTiles)
{
    extern __shared__ float smem[];
    constexpr int KQ = K / 4;
    float* ws   = smem;                 // K*256 : ws[k*256 + c]
    float* xs   = smem + K * FPC;       // K*64  : xs[k*64 + lr]
    float* ssum = xs + K * 64;          // 256
    float* ssq  = ssum + FPC;           // 256

    const int tid = threadIdx.x;
    const int tr = tid >> 5;            // 0..7 (warp id)
    const int tc = tid & 31;            // 0..31
    const int r0 = tr * 8;
    const int c0 = tc * 8;

    // Stage W transposed. Consecutive threads -> consecutive c: conflict-free STS.
    for (int idx = tid; idx < FPC * KQ; idx += 256) {
        int q = idx >> 8;               // 0..KQ-1
        int c = idx & 255;
        float4 v = Wg[c * KQ + q];
        ws[(4*q+0)*FPC + c] = v.x;
        ws[(4*q+1)*FPC + c] = v.y;
        ws[(4*q+2)*FPC + c] = v.z;
        ws[(4*q+3)*FPC + c] = v.w;
    }

    float bch[8];
    #pragma unroll
    for (int j = 0; j < 8; ++j) bch[j] = bias[c0 + j];

    // Per-thread channel stat partials, live across all tiles of this block.
    float sumc[8] = {0,0,0,0,0,0,0,0};
    float sqc [8] = {0,0,0,0,0,0,0,0};

    __syncthreads();

    for (int tile = blockIdx.x; tile < numTiles; tile += gridDim.x) {
        // Stage X transposed: xs[k*64 + lr]. Consecutive threads -> consecutive lr.
        for (int idx = tid; idx < 64 * KQ; idx += 256) {
            int lr = idx & 63;
            int q  = idx >> 6;          // 0..KQ-1
            int gr = tile * 64 + lr;
            float4 v;
            if (GATHER) {
                int b = gr >> 11;       // / (A*D)
                if (q < FA/4) {
                    int j = nl[gr];
                    v = af[(size_t)((b << 7) + j) * (FA/4) + q];
                } else {
                    int j = bl[gr];
                    v = bf[(size_t)((b << 8) + j) * (FB/4) + (q - FA/4)];
                }
            } else {
                v = af[(size_t)gr * KQ + q];
            }
            xs[(4*q+0)*64 + lr] = v.x;
            xs[(4*q+1)*64 + lr] = v.y;
            xs[(4*q+2)*64 + lr] = v.z;
            xs[(4*q+3)*64 + lr] = v.w;
        }
        __syncthreads();

        unsigned long long acc[8][4];
        #pragma unroll
        for (int i = 0; i < 8; ++i)
            #pragma unroll
            for (int j = 0; j < 4; ++j) acc[i][j] = 0ull;

        #pragma unroll 2
        for (int k = 0; k < K; ++k) {
            const float4 xa = *(const float4*)&xs[k*64 + r0];       // warp-broadcast
            const float4 xb = *(const float4*)&xs[k*64 + r0 + 4];
            const ulonglong2 w0 = *(const ulonglong2*)&ws[k*FPC + c0];
            const ulonglong2 w1 = *(const ulonglong2*)&ws[k*FPC + c0 + 4];
            unsigned long long xp[8];
            xp[0] = pack2(xa.x, xa.x); xp[1] = pack2(xa.y, xa.y);
            xp[2] = pack2(xa.z, xa.z); xp[3] = pack2(xa.w, xa.w);
            xp[4] = pack2(xb.x, xb.x); xp[5] = pack2(xb.y, xb.y);
            xp[6] = pack2(xb.z, xb.z); xp[7] = pack2(xb.w, xb.w);
            #pragma unroll
            for (int i = 0; i < 8; ++i) {
                fma2(acc[i][0], xp[i], w0.x);
                fma2(acc[i][1], xp[i], w0.y);
                fma2(acc[i][2], xp[i], w1.x);
                fma2(acc[i][3], xp[i], w1.y);
            }
        }

        // Epilogue: +bias, raw store, stat accumulation in registers.
        #pragma unroll
        for (int i = 0; i < 8; ++i) {
            float y[8];
            #pragma unroll
            for (int j = 0; j < 4; ++j) {
                float2 p = unpack2(acc[i][j]);
                y[2*j]   = p.x + bch[2*j];
                y[2*j+1] = p.y + bch[2*j+1];
            }
            #pragma unroll
            for (int j = 0; j < 8; ++j) { sumc[j] += y[j]; sqc[j] += y[j]*y[j]; }
            size_t row = (size_t)tile * 64 + r0 + i;
            float4* o = (float4*)&out[row * FPC + c0];
            o[0] = make_float4(y[0], y[1], y[2], y[3]);
            o[1] = make_float4(y[4], y[5], y[6], y[7]);
        }
        __syncthreads();  // protect xs against next tile's staging
    }

    // Flush stats: registers -> shared (atomic) -> global (one REDG pair/thread).
    ssum[tid] = 0.f; ssq[tid] = 0.f;
    __syncthreads();
    #pragma unroll
    for (int j = 0; j < 8; ++j) {
        atomicAdd(&ssum[c0 + j], sumc[j]);
        atomicAdd(&ssq [c0 + j], sqc[j]);
    }
    __syncthreads();
    atomicAdd(&g_sum[statsIdx][tid],   ssum[tid]);
    atomicAdd(&g_sqsum[statsIdx][tid], ssq[tid]);
}

// ---------------- finalize: per-channel scale/shift ----------------------
__global__ void finalize_stats_kernel(const float* __restrict__ gamma0,
                                      const float* __restrict__ beta0,
                                      const float* __restrict__ gamma1,
                                      const float* __restrict__ beta1) {
    int t = threadIdx.x;
    if (t >= FPC) return;
    {
        float n = (float)R_ATOM;
        float mean = g_sum[0][t] / n;
        float var  = g_sqsum[0][t] / n - mean * mean;
        float sc = gamma0[t] * rsqrtf(var + BN_EPS);
        g_scale[0][t] = sc;
        g_shift[0][t] = beta0[t] - mean * sc;
    }
    {
        float n = (float)R_NEI;
        float mean = g_sum[1][t] / n;
        float var  = g_sqsum[1][t] / n - mean * mean;
        float sc = gamma1[t] * rsqrtf(var + BN_EPS);
        g_scale[1][t] = sc;
        g_shift[1][t] = beta1[t] - mean * sc;
    }
}

// ---------------- normalize + leaky relu (in place, vectorized) ----------
__global__ void norm_leaky_kernel(float4* __restrict__ data, long long n4, int si) {
    const float4* sc4 = (const float4*)g_scale[si];
    const float4* sh4 = (const float4*)g_shift[si];
    long long i = (long long)blockIdx.x * blockDim.x + threadIdx.x;
    long long stride = (long long)gridDim.x * blockDim.x;
    for (; i < n4; i += stride) {
        float4 v = data[i];
        int cq = (int)(i & 63);        // 64 float4 per 256-channel row
        float4 s = sc4[cq];
        float4 h = sh4[cq];
        float a = v.x * s.x + h.x;
        float b = v.y * s.y + h.y;
        float c = v.z * s.z + h.z;
        float d = v.w * s.w + h.w;
        v.x = (a >= 0.f) ? a : SLOPE * a;
        v.y = (b >= 0.f) ? b : SLOPE * b;
        v.z = (c >= 0.f) ? c : SLOPE * c;
        v.w = (d >= 0.f) ? d : SLOPE * d;
        data[i] = v;
    }
}

// ---------------- launcher ------------------------------------------------
extern "C" void kernel_launch(void* const* d_in, const int* in_sizes, int n_in,
                              void* d_out, int out_size) {
    const float* atom_features = (const float*)d_in[0];
    const float* bond_features = (const float*)d_in[1];
    const int*   atom_nl       = (const int*)  d_in[2];
    const int*   bond_nl       = (const int*)  d_in[3];
    const float* atom_W        = (const float*)d_in[4];
    const float* atom_b        = (const float*)d_in[5];
    const float* atom_gamma    = (const float*)d_in[6];
    const float* atom_beta     = (const float*)d_in[7];
    const float* nei_W         = (const float*)d_in[8];
    const float* nei_b         = (const float*)d_in[9];
    const float* nei_gamma     = (const float*)d_in[10];
    const float* nei_beta      = (const float*)d_in[11];

    float* out_atom = (float*)d_out;
    float* out_nei  = (float*)d_out + ATOM_OUT_ELEMS;

    const int smem96 = (96*FPC + 96*64 + 2*FPC) * (int)sizeof(float);  // 124928 B
    const int smem64 = (64*FPC + 64*64 + 2*FPC) * (int)sizeof(float);  //  83968 B
    cudaFuncSetAttribute((const void*)gemm_bn_kernel<96, true>,
                         cudaFuncAttributeMaxDynamicSharedMemorySize, smem96);
    cudaFuncSetAttribute((const void*)gemm_bn_kernel<64, false>,
                         cudaFuncAttributeMaxDynamicSharedMemorySize, smem64);

    zero_stats_kernel<<<1, 256>>>();

    // atom branch: 512 tiles of 64 rows, K=64, no gather
    gemm_bn_kernel<64, false><<<456, 256, smem64>>>(
        (const float4*)atom_W, atom_b,
        (const float4*)atom_features, nullptr, nullptr, nullptr,
        out_atom, 0, R_ATOM / 64);

    // neighbor branch: 8192 tiles of 64 rows, K=96, gathered operands
    gemm_bn_kernel<96, true><<<456, 256, smem96>>>(
        (const float4*)nei_W, nei_b,
        (const float4*)atom_features, (const float4*)bond_features,
        atom_nl, bond_nl,
        out_nei, 1, R_NEI / 64);

    finalize_stats_kernel<<<1, 256>>>(atom_gamma, atom_beta, nei_gamma, nei_beta);

    norm_leaky_kernel<<<1024, 256>>>((float4*)out_atom, ATOM_OUT_ELEMS / 4, 0);
    norm_leaky_kernel<<<4096, 256>>>((float4*)out_nei,  NEI_OUT_ELEMS  / 4, 1);
}

// round 2
// speedup vs baseline: 1.0008x; 1.0008x over previous
#include <cuda_runtime.h>
#include <cstdint>
#include <cstddef>

// Problem constants
#define BATCH 256
#define ANUM  128
#define NBNUM 256
#define DNUM  16
#define FA    64
#define FB    32
#define FPC   256          // output channels
#define R_NEI  (BATCH*ANUM*DNUM)   // 524288 rows
#define R_ATOM (BATCH*ANUM)        // 32768 rows
#define ATOM_OUT_ELEMS ((long long)R_ATOM*FPC)   //   8,388,608
#define NEI_OUT_ELEMS  ((long long)R_NEI*FPC)    // 134,217,728
#define BN_EPS 1e-6f
#define SLOPE  0.01f

// ---------------- device scratch (no allocations allowed) ----------------
__device__ float g_sum[2][FPC];
__device__ float g_sqsum[2][FPC];
__device__ float g_scale[2][FPC];
__device__ float g_shift[2][FPC];

__global__ void zero_stats_kernel() {
    int t = threadIdx.x;
    if (t < FPC) {
        g_sum[0][t] = 0.f;  g_sum[1][t] = 0.f;
        g_sqsum[0][t] = 0.f; g_sqsum[1][t] = 0.f;
    }
}

// ---------------- packed f32x2 helpers (FFMA2 only reachable via PTX) ----
__device__ __forceinline__ unsigned long long pack2(float lo, float hi) {
    unsigned long long r;
    asm("mov.b64 %0, {%1,%2};" : "=l"(r) : "f"(lo), "f"(hi));
    return r;
}
__device__ __forceinline__ void fma2(unsigned long long& d,
                                     unsigned long long a,
                                     unsigned long long b) {
    asm("fma.rn.f32x2 %0, %1, %2, %0;" : "+l"(d) : "l"(a), "l"(b));
}
__device__ __forceinline__ float2 unpack2(unsigned long long v) {
    float2 r;
    asm("mov.b64 {%0,%1}, %2;" : "=f"(r.x), "=f"(r.y) : "l"(v));
    return r;
}

// ---------------- fused GEMM + raw store + channel-stat accumulation -----
// Tile: 64 rows x 256 channels per block, 256 threads.
// Thread (tr=tid>>5, tc=tid&31) owns rows [tr*8, tr*8+8) x channels [tc*8, tc*8+8).
// W staged transposed in shared once per block; grid-stride over row tiles.
template<int K, bool GATHER>
__global__ __launch_bounds__(256, 1)
void gemm_bn_kernel(const float4* __restrict__ Wg,   // [FPC][K/4]
                    const float*  __restrict__ bias, // [FPC]
                    const float4* __restrict__ af,   // GATHER: atom feats [B*A][FA/4]; else rows [R][K/4]
                    const float4* __restrict__ bf,   // GATHER: bond feats [B*NB][FB/4]
                    const int*    __restrict__ nl,   // [R_NEI]
                    const int*    __restrict__ bl,   // [R_NEI]
                    float*        __restrict__ out,
                    int statsIdx, int numTiles)
{
    extern __shared__ float smem[];
    constexpr int KQ = K / 4;
    float* ws   = smem;                 // K*256 : ws[k*256 + c]
    float* xs   = smem + K * FPC;       // K*64  : xs[k*64 + lr]
    float* ssum = xs + K * 64;          // 256
    float* ssq  = ssum + FPC;           // 256

    const int tid = threadIdx.x;
    const int tr = tid >> 5;            // 0..7 (warp id)
    const int tc = tid & 31;            // 0..31
    const int r0 = tr * 8;
    const int c0 = tc * 8;

    // Stage W transposed. Consecutive threads -> consecutive c: conflict-free STS.
    for (int idx = tid; idx < FPC * KQ; idx += 256) {
        int q = idx >> 8;               // 0..KQ-1
        int c = idx & 255;
        float4 v = Wg[c * KQ + q];
        ws[(4*q+0)*FPC + c] = v.x;
        ws[(4*q+1)*FPC + c] = v.y;
        ws[(4*q+2)*FPC + c] = v.z;
        ws[(4*q+3)*FPC + c] = v.w;
    }

    float bch[8];
    #pragma unroll
    for (int j = 0; j < 8; ++j) bch[j] = bias[c0 + j];

    // Per-thread channel stat partials, live across all tiles of this block.
    float sumc[8] = {0,0,0,0,0,0,0,0};
    float sqc [8] = {0,0,0,0,0,0,0,0};

    __syncthreads();

    for (int tile = blockIdx.x; tile < numTiles; tile += gridDim.x) {
        // Stage X transposed: xs[k*64 + lr]. Consecutive threads -> consecutive lr.
        for (int idx = tid; idx < 64 * KQ; idx += 256) {
            int lr = idx & 63;
            int q  = idx >> 6;          // 0..KQ-1
            int gr = tile * 64 + lr;
            float4 v;
            if (GATHER) {
                int b = gr >> 11;       // / (A*D)
                if (q < FA/4) {
                    int j = nl[gr];
                    v = af[(size_t)((b << 7) + j) * (FA/4) + q];
                } else {
                    int j = bl[gr];
                    v = bf[(size_t)((b << 8) + j) * (FB/4) + (q - FA/4)];
                }
            } else {
                v = af[(size_t)gr * KQ + q];
            }
            xs[(4*q+0)*64 + lr] = v.x;
            xs[(4*q+1)*64 + lr] = v.y;
            xs[(4*q+2)*64 + lr] = v.z;
            xs[(4*q+3)*64 + lr] = v.w;
        }
        __syncthreads();

        unsigned long long acc[8][4];
        #pragma unroll
        for (int i = 0; i < 8; ++i)
            #pragma unroll
            for (int j = 0; j < 4; ++j) acc[i][j] = 0ull;

        #pragma unroll 2
        for (int k = 0; k < K; ++k) {
            const float4 xa = *(const float4*)&xs[k*64 + r0];       // warp-broadcast
            const float4 xb = *(const float4*)&xs[k*64 + r0 + 4];
            const ulonglong2 w0 = *(const ulonglong2*)&ws[k*FPC + c0];
            const ulonglong2 w1 = *(const ulonglong2*)&ws[k*FPC + c0 + 4];
            unsigned long long xp[8];
            xp[0] = pack2(xa.x, xa.x); xp[1] = pack2(xa.y, xa.y);
            xp[2] = pack2(xa.z, xa.z); xp[3] = pack2(xa.w, xa.w);
            xp[4] = pack2(xb.x, xb.x); xp[5] = pack2(xb.y, xb.y);
            xp[6] = pack2(xb.z, xb.z); xp[7] = pack2(xb.w, xb.w);
            #pragma unroll
            for (int i = 0; i < 8; ++i) {
                fma2(acc[i][0], xp[i], w0.x);
                fma2(acc[i][1], xp[i], w0.y);
                fma2(acc[i][2], xp[i], w1.x);
                fma2(acc[i][3], xp[i], w1.y);
            }
        }

        // Epilogue: +bias, raw store, stat accumulation in registers.
        #pragma unroll
        for (int i = 0; i < 8; ++i) {
            float y[8];
            #pragma unroll
            for (int j = 0; j < 4; ++j) {
                float2 p = unpack2(acc[i][j]);
                y[2*j]   = p.x + bch[2*j];
                y[2*j+1] = p.y + bch[2*j+1];
            }
            #pragma unroll
            for (int j = 0; j < 8; ++j) { sumc[j] += y[j]; sqc[j] += y[j]*y[j]; }
            size_t row = (size_t)tile * 64 + r0 + i;
            float4* o = (float4*)&out[row * FPC + c0];
            o[0] = make_float4(y[0], y[1], y[2], y[3]);
            o[1] = make_float4(y[4], y[5], y[6], y[7]);
        }
        __syncthreads();  // protect xs against next tile's staging
    }

    // Flush stats: registers -> shared (atomic) -> global (one REDG pair/thread).
    ssum[tid] = 0.f; ssq[tid] = 0.f;
    __syncthreads();
    #pragma unroll
    for (int j = 0; j < 8; ++j) {
        atomicAdd(&ssum[c0 + j], sumc[j]);
        atomicAdd(&ssq [c0 + j], sqc[j]);
    }
    __syncthreads();
    atomicAdd(&g_sum[statsIdx][tid],   ssum[tid]);
    atomicAdd(&g_sqsum[statsIdx][tid], ssq[tid]);
}

// ---------------- finalize: per-channel scale/shift ----------------------
__global__ void finalize_stats_kernel(const float* __restrict__ gamma0,
                                      const float* __restrict__ beta0,
                                      const float* __restrict__ gamma1,
                                      const float* __restrict__ beta1) {
    int t = threadIdx.x;
    if (t >= FPC) return;
    {
        float n = (float)R_ATOM;
        float mean = g_sum[0][t] / n;
        float var  = g_sqsum[0][t] / n - mean * mean;
        float sc = gamma0[t] * rsqrtf(var + BN_EPS);
        g_scale[0][t] = sc;
        g_shift[0][t] = beta0[t] - mean * sc;
    }
    {
        float n = (float)R_NEI;
        float mean = g_sum[1][t] / n;
        float var  = g_sqsum[1][t] / n - mean * mean;
        float sc = gamma1[t] * rsqrtf(var + BN_EPS);
        g_scale[1][t] = sc;
        g_shift[1][t] = beta1[t] - mean * sc;
    }
}

// ---------------- normalize + leaky relu (in place, vectorized) ----------
__global__ void norm_leaky_kernel(float4* __restrict__ data, long long n4, int si) {
    const float4* sc4 = (const float4*)g_scale[si];
    const float4* sh4 = (const float4*)g_shift[si];
    long long i = (long long)blockIdx.x * blockDim.x + threadIdx.x;
    long long stride = (long long)gridDim.x * blockDim.x;
    for (; i < n4; i += stride) {
        float4 v = data[i];
        int cq = (int)(i & 63);        // 64 float4 per 256-channel row
        float4 s = sc4[cq];
        float4 h = sh4[cq];
        float a = v.x * s.x + h.x;
        float b = v.y * s.y + h.y;
        float c = v.z * s.z + h.z;
        float d = v.w * s.w + h.w;
        v.x = (a >= 0.f) ? a : SLOPE * a;
        v.y = (b >= 0.f) ? b : SLOPE * b;
        v.z = (c >= 0.f) ? c : SLOPE * c;
        v.w = (d >= 0.f) ? d : SLOPE * d;
        data[i] = v;
    }
}

// ---------------- launcher ------------------------------------------------
extern "C" void kernel_launch(void* const* d_in, const int* in_sizes, int n_in,
                              void* d_out, int out_size) {
    const float* atom_features = (const float*)d_in[0];
    const float* bond_features = (const float*)d_in[1];
    const int*   atom_nl       = (const int*)  d_in[2];
    const int*   bond_nl       = (const int*)  d_in[3];
    const float* atom_W        = (const float*)d_in[4];
    const float* atom_b        = (const float*)d_in[5];
    const float* atom_gamma    = (const float*)d_in[6];
    const float* atom_beta     = (const float*)d_in[7];
    const float* nei_W         = (const float*)d_in[8];
    const float* nei_b         = (const float*)d_in[9];
    const float* nei_gamma     = (const float*)d_in[10];
    const float* nei_beta      = (const float*)d_in[11];

    float* out_atom = (float*)d_out;
    float* out_nei  = (float*)d_out + ATOM_OUT_ELEMS;

    const int smem96 = (96*FPC + 96*64 + 2*FPC) * (int)sizeof(float);  // 124928 B
    const int smem64 = (64*FPC + 64*64 + 2*FPC) * (int)sizeof(float);  //  83968 B
    cudaFuncSetAttribute((const void*)gemm_bn_kernel<96, true>,
                         cudaFuncAttributeMaxDynamicSharedMemorySize, smem96);
    cudaFuncSetAttribute((const void*)gemm_bn_kernel<64, false>,
                         cudaFuncAttributeMaxDynamicSharedMemorySize, smem64);

    zero_stats_kernel<<<1, 256>>>();

    // atom branch: 512 tiles of 64 rows, K=64, no gather
    gemm_bn_kernel<64, false><<<456, 256, smem64>>>(
        (const float4*)atom_W, atom_b,
        (const float4*)atom_features, nullptr, nullptr, nullptr,
        out_atom, 0, R_ATOM / 64);

    // neighbor branch: 8192 tiles of 64 rows, K=96, gathered operands
    gemm_bn_kernel<96, true><<<456, 256, smem96>>>(
        (const float4*)nei_W, nei_b,
        (const float4*)atom_features, (const float4*)bond_features,
        atom_nl, bond_nl,
        out_nei, 1, R_NEI / 64);

    finalize_stats_kernel<<<1, 256>>>(atom_gamma, atom_beta, nei_gamma, nei_beta);

    norm_leaky_kernel<<<1024, 256>>>((float4*)out_atom, ATOM_OUT_ELEMS / 4, 0);
    norm_leaky_kernel<<<4096, 256>>>((float4*)out_nei,  NEI_OUT_ELEMS  / 4, 1);
}

// round 3
// speedup vs baseline: 2.3152x; 2.3133x over previous
#include <cuda_runtime.h>
#include <cstdint>
#include <cstddef>

// Problem constants
#define BATCH 256
#define ANUM  128
#define NBNUM 256
#define DNUM  16
#define FA    64
#define FB    32
#define FPC   256          // output channels
#define R_NEI  (BATCH*ANUM*DNUM)   // 524288 rows
#define R_ATOM (BATCH*ANUM)        // 32768 rows
#define R_BOND (BATCH*NBNUM)       // 65536 rows
#define ATOM_OUT_ELEMS ((long long)R_ATOM*FPC)   //   8,388,608
#define NEI_OUT_ELEMS  ((long long)R_NEI*FPC)    // 134,217,728
#define BN_EPS 1e-6f
#define SLOPE  0.01f

// ---------------- device scratch (no allocations allowed) ----------------
__device__ float g_sum[2][FPC];
__device__ float g_sqsum[2][FPC];
__device__ float g_scale[2][FPC];
__device__ float g_shift[2][FPC];

// Precomputed per-atom and per-bond projections through nei_W halves.
__device__ float g_P[(size_t)R_ATOM * FPC];   // 33.5 MB
__device__ float g_Q[(size_t)R_BOND * FPC];   // 67 MB

__global__ void zero_stats_kernel() {
    int t = threadIdx.x;
    if (t < FPC) {
        g_sum[0][t] = 0.f;  g_sum[1][t] = 0.f;
        g_sqsum[0][t] = 0.f; g_sqsum[1][t] = 0.f;
    }
}

// ---------------- packed f32x2 helpers (FFMA2 only reachable via PTX) ----
__device__ __forceinline__ unsigned long long pack2(float lo, float hi) {
    unsigned long long r;
    asm("mov.b64 %0, {%1,%2};" : "=l"(r) : "f"(lo), "f"(hi));
    return r;
}
__device__ __forceinline__ void fma2(unsigned long long& d,
                                     unsigned long long a,
                                     unsigned long long b) {
    asm("fma.rn.f32x2 %0, %1, %2, %0;" : "+l"(d) : "l"(a), "l"(b));
}
__device__ __forceinline__ float2 unpack2(unsigned long long v) {
    float2 r;
    asm("mov.b64 {%0,%1}, %2;" : "=f"(r.x), "=f"(r.y) : "l"(v));
    return r;
}

// ---------------- dense GEMM: out[r][c] = W[c] . X[r] (+bias, +stats) ----
// Tile: 64 rows x 256 channels, 256 threads. Thread (tr,tc) owns 8x8.
// W staged transposed once per block; grid-stride over row tiles.
// wldq/woffq select a column slice of a wider W matrix (float4 units).
template<int K, bool STATS>
__global__ __launch_bounds__(256, 1)
void gemm_kernel(const float4* __restrict__ Wg, int wldq, int woffq,
                 const float*  __restrict__ bias,
                 const float4* __restrict__ X,     // [R][K/4]
                 float*        __restrict__ out,
                 int statsIdx, int numTiles)
{
    extern __shared__ float smem[];
    constexpr int KQ = K / 4;
    float* ws   = smem;                 // K*256 : ws[k*256 + c]
    float* xs   = smem + K * FPC;       // K*64  : xs[k*64 + lr]
    float* ssum = xs + K * 64;          // 256 (STATS only)
    float* ssq  = ssum + FPC;           // 256

    const int tid = threadIdx.x;
    const int tr = tid >> 5;
    const int tc = tid & 31;
    const int r0 = tr * 8;
    const int c0 = tc * 8;

    for (int idx = tid; idx < FPC * KQ; idx += 256) {
        int q = idx >> 8;
        int c = idx & 255;
        float4 v = Wg[(size_t)c * wldq + woffq + q];
        ws[(4*q+0)*FPC + c] = v.x;
        ws[(4*q+1)*FPC + c] = v.y;
        ws[(4*q+2)*FPC + c] = v.z;
        ws[(4*q+3)*FPC + c] = v.w;
    }

    float bch[8];
    float sumc[8], sqc[8];
    if (STATS) {
        #pragma unroll
        for (int j = 0; j < 8; ++j) { bch[j] = bias[c0 + j]; sumc[j] = 0.f; sqc[j] = 0.f; }
    }

    __syncthreads();

    for (int tile = blockIdx.x; tile < numTiles; tile += gridDim.x) {
        for (int idx = tid; idx < 64 * KQ; idx += 256) {
            int lr = idx & 63;
            int q  = idx >> 6;
            int gr = tile * 64 + lr;
            float4 v = X[(size_t)gr * KQ + q];
            xs[(4*q+0)*64 + lr] = v.x;
            xs[(4*q+1)*64 + lr] = v.y;
            xs[(4*q+2)*64 + lr] = v.z;
            xs[(4*q+3)*64 + lr] = v.w;
        }
        __syncthreads();

        unsigned long long acc[8][4];
        #pragma unroll
        for (int i = 0; i < 8; ++i)
            #pragma unroll
            for (int j = 0; j < 4; ++j) acc[i][j] = 0ull;

        #pragma unroll 2
        for (int k = 0; k < K; ++k) {
            const float4 xa = *(const float4*)&xs[k*64 + r0];
            const float4 xb = *(const float4*)&xs[k*64 + r0 + 4];
            const ulonglong2 w0 = *(const ulonglong2*)&ws[k*FPC + c0];
            const ulonglong2 w1 = *(const ulonglong2*)&ws[k*FPC + c0 + 4];
            unsigned long long xp[8];
            xp[0] = pack2(xa.x, xa.x); xp[1] = pack2(xa.y, xa.y);
            xp[2] = pack2(xa.z, xa.z); xp[3] = pack2(xa.w, xa.w);
            xp[4] = pack2(xb.x, xb.x); xp[5] = pack2(xb.y, xb.y);
            xp[6] = pack2(xb.z, xb.z); xp[7] = pack2(xb.w, xb.w);
            #pragma unroll
            for (int i = 0; i < 8; ++i) {
                fma2(acc[i][0], xp[i], w0.x);
                fma2(acc[i][1], xp[i], w0.y);
                fma2(acc[i][2], xp[i], w1.x);
                fma2(acc[i][3], xp[i], w1.y);
            }
        }

        #pragma unroll
        for (int i = 0; i < 8; ++i) {
            float y[8];
            #pragma unroll
            for (int j = 0; j < 4; ++j) {
                float2 p = unpack2(acc[i][j]);
                y[2*j]   = p.x;
                y[2*j+1] = p.y;
            }
            if (STATS) {
                #pragma unroll
                for (int j = 0; j < 8; ++j) {
                    y[j] += bch[j];
                    sumc[j] += y[j]; sqc[j] += y[j]*y[j];
                }
            }
            size_t row = (size_t)tile * 64 + r0 + i;
            float4* o = (float4*)&out[row * FPC + c0];
            o[0] = make_float4(y[0], y[1], y[2], y[3]);
            o[1] = make_float4(y[4], y[5], y[6], y[7]);
        }
        __syncthreads();
    }

    if (STATS) {
        ssum[tid] = 0.f; ssq[tid] = 0.f;
        __syncthreads();
        #pragma unroll
        for (int j = 0; j < 8; ++j) {
            atomicAdd(&ssum[c0 + j], sumc[j]);
            atomicAdd(&ssq [c0 + j], sqc[j]);
        }
        __syncthreads();
        atomicAdd(&g_sum[statsIdx][tid],   ssum[tid]);
        atomicAdd(&g_sqsum[statsIdx][tid], ssq[tid]);
    }
}

// ---------------- nei stats: per-channel sum/sqsum of t = P[a]+Q[b] ------
// One warp per row; lane l owns channels [l*4, l*4+4) and [128+l*4, ...).
__global__ __launch_bounds__(256, 8)
void nei_stats_kernel(const int* __restrict__ nl, const int* __restrict__ bl) {
    __shared__ float ssum[FPC], ssq[FPC];
    const int tid = threadIdx.x;
    const int lane = tid & 31;
    const int gw = (blockIdx.x * blockDim.x + tid) >> 5;
    const int nw = (gridDim.x * blockDim.x) >> 5;

    float s1[8] = {0,0,0,0,0,0,0,0};
    float s2[8] = {0,0,0,0,0,0,0,0};

    for (int r = gw; r < R_NEI; r += 2*nw) {
        int r1 = r + nw;
        int ia0=0, ib0=0, ia1=0, ib1=0;
        if (lane == 0) {
            ia0 = nl[r]; ib0 = bl[r];
            if (r1 < R_NEI) { ia1 = nl[r1]; ib1 = bl[r1]; }
        }
        ia0 = __shfl_sync(0xffffffffu, ia0, 0);
        ib0 = __shfl_sync(0xffffffffu, ib0, 0);
        ia1 = __shfl_sync(0xffffffffu, ia1, 0);
        ib1 = __shfl_sync(0xffffffffu, ib1, 0);

        {
            int b = r >> 11;
            const float4* prow = (const float4*)&g_P[((size_t)((b<<7) + ia0)) * FPC];
            const float4* qrow = (const float4*)&g_Q[((size_t)((b<<8) + ib0)) * FPC];
            float4 p0 = prow[lane], p1 = prow[lane+32];
            float4 q0 = qrow[lane], q1 = qrow[lane+32];
            float t[8] = {p0.x+q0.x, p0.y+q0.y, p0.z+q0.z, p0.w+q0.w,
                          p1.x+q1.x, p1.y+q1.y, p1.z+q1.z, p1.w+q1.w};
            #pragma unroll
            for (int j = 0; j < 8; ++j) { s1[j] += t[j]; s2[j] += t[j]*t[j]; }
        }
        if (r1 < R_NEI) {
            int b = r1 >> 11;
            const float4* prow = (const float4*)&g_P[((size_t)((b<<7) + ia1)) * FPC];
            const float4* qrow = (const float4*)&g_Q[((size_t)((b<<8) + ib1)) * FPC];
            float4 p0 = prow[lane], p1 = prow[lane+32];
            float4 q0 = qrow[lane], q1 = qrow[lane+32];
            float t[8] = {p0.x+q0.x, p0.y+q0.y, p0.z+q0.z, p0.w+q0.w,
                          p1.x+q1.x, p1.y+q1.y, p1.z+q1.z, p1.w+q1.w};
            #pragma unroll
            for (int j = 0; j < 8; ++j) { s1[j] += t[j]; s2[j] += t[j]*t[j]; }
        }
    }

    if (tid < FPC) { ssum[tid] = 0.f; ssq[tid] = 0.f; }
    __syncthreads();
    #pragma unroll
    for (int j = 0; j < 4; ++j) {
        atomicAdd(&ssum[lane*4 + j],       s1[j]);
        atomicAdd(&ssum[128 + lane*4 + j], s1[4+j]);
        atomicAdd(&ssq [lane*4 + j],       s2[j]);
        atomicAdd(&ssq [128 + lane*4 + j], s2[4+j]);
    }
    __syncthreads();
    if (tid < FPC) {
        atomicAdd(&g_sum[1][tid],   ssum[tid]);
        atomicAdd(&g_sqsum[1][tid], ssq[tid]);
    }
}

// ---------------- finalize: per-channel scale/shift ----------------------
__global__ void finalize_stats_kernel(const float* __restrict__ gamma0,
                                      const float* __restrict__ beta0,
                                      const float* __restrict__ gamma1,
                                      const float* __restrict__ beta1) {
    int t = threadIdx.x;
    if (t >= FPC) return;
    {   // atom branch: stats of y (bias included)
        float n = (float)R_ATOM;
        float mean = g_sum[0][t] / n;
        float var  = g_sqsum[0][t] / n - mean * mean;
        float sc = gamma0[t] * rsqrtf(var + BN_EPS);
        g_scale[0][t] = sc;
        g_shift[0][t] = beta0[t] - mean * sc;
    }
    {   // nei branch: stats of t = p+q. Bias cancels: y-mean(y) = t-mean(t).
        float n = (float)R_NEI;
        float m1  = g_sum[1][t] / n;
        float var = g_sqsum[1][t] / n - m1 * m1;
        float sc = gamma1[t] * rsqrtf(var + BN_EPS);
        g_scale[1][t] = sc;
        g_shift[1][t] = beta1[t] - m1 * sc;
    }
}

// ---------------- nei output: normalize(P[a]+Q[b]) + leaky, single write -
__global__ __launch_bounds__(256, 8)
void nei_out_kernel(const int* __restrict__ nl, const int* __restrict__ bl,
                    float* __restrict__ out) {
    const int tid = threadIdx.x;
    const int lane = tid & 31;
    const int gw = (blockIdx.x * blockDim.x + tid) >> 5;
    const int nw = (gridDim.x * blockDim.x) >> 5;

    const float4* sc4 = (const float4*)g_scale[1];
    const float4* sh4 = (const float4*)g_shift[1];
    float4 s0 = sc4[lane], s1 = sc4[lane+32];
    float4 h0 = sh4[lane], h1 = sh4[lane+32];

    for (int r = gw; r < R_NEI; r += nw) {
        int ia = 0, ib = 0;
        if (lane == 0) { ia = nl[r]; ib = bl[r]; }
        ia = __shfl_sync(0xffffffffu, ia, 0);
        ib = __shfl_sync(0xffffffffu, ib, 0);
        int b = r >> 11;
        const float4* prow = (const float4*)&g_P[((size_t)((b<<7) + ia)) * FPC];
        const float4* qrow = (const float4*)&g_Q[((size_t)((b<<8) + ib)) * FPC];
        float4 p0 = prow[lane], p1 = prow[lane+32];
        float4 q0 = qrow[lane], q1 = qrow[lane+32];

        float4 v0, v1;
        v0.x = (p0.x+q0.x)*s0.x + h0.x;  v0.y = (p0.y+q0.y)*s0.y + h0.y;
        v0.z = (p0.z+q0.z)*s0.z + h0.z;  v0.w = (p0.w+q0.w)*s0.w + h0.w;
        v1.x = (p1.x+q1.x)*s1.x + h1.x;  v1.y = (p1.y+q1.y)*s1.y + h1.y;
        v1.z = (p1.z+q1.z)*s1.z + h1.z;  v1.w = (p1.w+q1.w)*s1.w + h1.w;
        v0.x = v0.x >= 0.f ? v0.x : SLOPE*v0.x;
        v0.y = v0.y >= 0.f ? v0.y : SLOPE*v0.y;
        v0.z = v0.z >= 0.f ? v0.z : SLOPE*v0.z;
        v0.w = v0.w >= 0.f ? v0.w : SLOPE*v0.w;
        v1.x = v1.x >= 0.f ? v1.x : SLOPE*v1.x;
        v1.y = v1.y >= 0.f ? v1.y : SLOPE*v1.y;
        v1.z = v1.z >= 0.f ? v1.z : SLOPE*v1.z;
        v1.w = v1.w >= 0.f ? v1.w : SLOPE*v1.w;

        float4* o = (float4*)&out[(size_t)r * FPC];
        o[lane]      = v0;
        o[lane + 32] = v1;
    }
}

// ---------------- normalize + leaky relu (atom branch, in place) ---------
__global__ void norm_leaky_kernel(float4* __restrict__ data, long long n4, int si) {
    const float4* sc4 = (const float4*)g_scale[si];
    const float4* sh4 = (const float4*)g_shift[si];
    long long i = (long long)blockIdx.x * blockDim.x + threadIdx.x;
    long long stride = (long long)gridDim.x * blockDim.x;
    for (; i < n4; i += stride) {
        float4 v = data[i];
        int cq = (int)(i & 63);
        float4 s = sc4[cq];
        float4 h = sh4[cq];
        float a = v.x * s.x + h.x;
        float b = v.y * s.y + h.y;
        float c = v.z * s.z + h.z;
        float d = v.w * s.w + h.w;
        v.x = (a >= 0.f) ? a : SLOPE * a;
        v.y = (b >= 0.f) ? b : SLOPE * b;
        v.z = (c >= 0.f) ? c : SLOPE * c;
        v.w = (d >= 0.f) ? d : SLOPE * d;
        data[i] = v;
    }
}

// ---------------- launcher ------------------------------------------------
extern "C" void kernel_launch(void* const* d_in, const int* in_sizes, int n_in,
                              void* d_out, int out_size) {
    const float* atom_features = (const float*)d_in[0];
    const float* bond_features = (const float*)d_in[1];
    const int*   atom_nl       = (const int*)  d_in[2];
    const int*   bond_nl       = (const int*)  d_in[3];
    const float* atom_W        = (const float*)d_in[4];
    const float* atom_b        = (const float*)d_in[5];
    const float* atom_gamma    = (const float*)d_in[6];
    const float* atom_beta     = (const float*)d_in[7];
    const float* nei_W         = (const float*)d_in[8];
    const float* nei_gamma     = (const float*)d_in[10];
    const float* nei_beta      = (const float*)d_in[11];

    float* out_atom = (float*)d_out;
    float* out_nei  = (float*)d_out + ATOM_OUT_ELEMS;

    float *pP = nullptr, *pQ = nullptr;
    cudaGetSymbolAddress((void**)&pP, g_P);
    cudaGetSymbolAddress((void**)&pQ, g_Q);

    const int smem64s = (64*FPC + 64*64 + 2*FPC) * (int)sizeof(float);  // 83968
    const int smem64  = (64*FPC + 64*64) * (int)sizeof(float);          // 81920
    const int smem32  = (32*FPC + 32*64) * (int)sizeof(float);          // 40960
    cudaFuncSetAttribute((const void*)gemm_kernel<64, true>,
                         cudaFuncAttributeMaxDynamicSharedMemorySize, smem64s);
    cudaFuncSetAttribute((const void*)gemm_kernel<64, false>,
                         cudaFuncAttributeMaxDynamicSharedMemorySize, smem64);
    cudaFuncSetAttribute((const void*)gemm_kernel<32, false>,
                         cudaFuncAttributeMaxDynamicSharedMemorySize, smem32);

    zero_stats_kernel<<<1, 256>>>();

    // atom branch: raw y + stats[0]   (W stride 64 floats = 16 float4)
    gemm_kernel<64, true><<<456, 256, smem64s>>>(
        (const float4*)atom_W, 16, 0, atom_b,
        (const float4*)atom_features, out_atom, 0, R_ATOM / 64);

    // P = atom_features @ Wa^T  (nei_W cols 0..63; row stride 96 floats = 24 f4)
    gemm_kernel<64, false><<<456, 256, smem64>>>(
        (const float4*)nei_W, 24, 0, nullptr,
        (const float4*)atom_features, pP, 0, R_ATOM / 64);

    // Q = bond_features @ Wb^T  (nei_W cols 64..95)
    gemm_kernel<32, false><<<456, 256, smem32>>>(
        (const float4*)nei_W, 24, 16, nullptr,
        (const float4*)bond_features, pQ, 0, R_BOND / 64);

    // nei stats over t = P[a]+Q[b]
    nei_stats_kernel<<<1024, 256>>>(atom_nl, bond_nl);

    finalize_stats_kernel<<<1, 256>>>(atom_gamma, atom_beta, nei_gamma, nei_beta);

    // atom: normalize in place (34 MB)
    norm_leaky_kernel<<<512, 256>>>((float4*)out_atom, ATOM_OUT_ELEMS / 4, 0);

    // nei: gather + normalize + leaky, single write of 537 MB
    nei_out_kernel<<<2048, 256>>>(atom_nl, bond_nl, out_nei);
}